// round 14
// baseline (speedup 1.0000x reference)
#include <cuda_runtime.h>
#include <cuda_fp16.h>
#include <cstdint>
#include <cstddef>

// ---------------- problem dims ----------------
#define A_DIM 4
#define M_DIM 1024
#define H_DIM 1024
#define E_DIM 8
#define N_DIM 4096
#define SPLITK_C 4

// ---------------- tile config ----------------
#define BM 128
#define BN 128
#define BKH 64
#define NSTAGE 3
#define NTHREADS 128
#define LDA_W 36
#define LDB_H 136
#define A_STG_WORDS (BM * LDA_W)
#define B_STG_WORDS (BKH * LDB_H / 2)
#define STG_WORDS   (A_STG_WORDS + B_STG_WORDS)
#define STG_BYTES   (STG_WORDS * 4)                /* 35840 B */
#define SMEM_DYN    (NSTAGE * STG_BYTES)           /* 107520 B -> 2 CTA/SM */
#define GRID_P      296

// ---------------- device scratch ----------------
__device__ uint32_t g_w1h[(size_t)E_DIM * H_DIM * (N_DIM / 2)];
__device__ __half   g_w2h[(size_t)E_DIM * N_DIM * H_DIM];
__device__ uint32_t g_xh [(size_t)A_DIM * M_DIM * (H_DIM / 2)];
__device__ __half   g_part[(size_t)E_DIM * SPLITK_C * H_DIM * H_DIM];
__device__ __half   g_wsh[(size_t)H_DIM * H_DIM];
__device__ int      g_ready[E_DIM];

// ---------------- helpers ----------------
__device__ __forceinline__ uint32_t smem_u32(const void* p) {
    uint32_t a;
    asm("{ .reg .u64 t; cvta.to.shared.u64 t, %1; cvt.u32.u64 %0, t; }" : "=r"(a) : "l"(p));
    return a;
}
__device__ __forceinline__ uint32_t pack_h2(float lo, float hi) {
    __half2 h = __float22half2_rn(make_float2(lo, hi));
    return *reinterpret_cast<uint32_t*>(&h);
}
__device__ __forceinline__ void cp16(uint32_t dst, const void* src) {
    asm volatile("cp.async.cg.shared.global [%0], [%1], 16;\n"
                 :: "r"(dst), "l"(__cvta_generic_to_global(src)) : "memory");
}
__device__ __forceinline__ void mma_f16(float* c, const uint32_t* a, const uint32_t* b) {
    asm volatile(
        "mma.sync.aligned.m16n8k16.row.col.f32.f16.f16.f32 "
        "{%0,%1,%2,%3}, {%4,%5,%6,%7}, {%8,%9}, {%0,%1,%2,%3};"
        : "+f"(c[0]), "+f"(c[1]), "+f"(c[2]), "+f"(c[3])
        : "r"(a[0]), "r"(a[1]), "r"(a[2]), "r"(a[3]), "r"(b[0]), "r"(b[1]));
}
__device__ __forceinline__ void ldsm4(uint32_t addr, uint32_t* r) {
    asm volatile("ldmatrix.sync.aligned.m8n8.x4.shared.b16 {%0,%1,%2,%3}, [%4];"
                 : "=r"(r[0]), "=r"(r[1]), "=r"(r[2]), "=r"(r[3]) : "r"(addr));
}
__device__ __forceinline__ void ldsm4t(uint32_t addr, uint32_t& r0, uint32_t& r1,
                                       uint32_t& r2, uint32_t& r3) {
    asm volatile("ldmatrix.sync.aligned.m8n8.x4.trans.shared.b16 {%0,%1,%2,%3}, [%4];"
                 : "=r"(r0), "=r"(r1), "=r"(r2), "=r"(r3) : "r"(addr));
}

// ---- in-kernel conversion of one expert's weights (grid-strided) ----
__device__ __forceinline__ void convert_expert(int e, int cta, int tid,
                                               const float* __restrict__ x,
                                               const float* __restrict__ w1,
                                               const float* __restrict__ w2) {
    const size_t stride = (size_t)GRID_P * NTHREADS;
    const size_t base = (size_t)cta * NTHREADS + tid;
    const size_t F = (size_t)H_DIM * N_DIM / 4;     // float4 per expert (w1 and w2)

    const float4* s1 = (const float4*)(w1 + (size_t)e * H_DIM * N_DIM);
    uint2* d1 = (uint2*)g_w1h + (size_t)e * F;
    for (size_t i = base; i < F; i += stride) {
        float4 v = s1[i];
        d1[i] = make_uint2(pack_h2(v.x, v.y), pack_h2(v.z, v.w));
    }
    const float4* s2 = (const float4*)(w2 + (size_t)e * N_DIM * H_DIM);
    uint2* d2 = (uint2*)g_w2h + (size_t)e * F;
    for (size_t i = base; i < F; i += stride) {
        float4 v = s2[i];
        d2[i] = make_uint2(pack_h2(v.x, v.y), pack_h2(v.z, v.w));
    }
    if (e == 0) {
        const size_t FX = (size_t)A_DIM * M_DIM * H_DIM / 4;
        const float4* sx = (const float4*)x;
        uint2* dx = (uint2*)g_xh;
        for (size_t i = base; i < FX; i += stride) {
            float4 v = sx[i];
            dx[i] = make_uint2(pack_h2(v.x, v.y), pack_h2(v.z, v.w));
        }
    }
    __syncthreads();
    __threadfence();
    if (tid == 0) atomicAdd(&g_ready[e], 1);
}

__device__ __forceinline__ void wait_expert(int e, int tid) {
    if (tid == 0) {
        while (*(volatile int*)&g_ready[e] < GRID_P) __nanosleep(128);
        __threadfence();
    }
    __syncthreads();
}

__global__ void zero_flags_ker() {
    if (threadIdx.x < E_DIM) g_ready[threadIdx.x] = 0;
}

// =============================================================================
// Persistent fp16 GEMM. CONV: fused producer converting fp32->fp16 per expert.
// =============================================================================
template <int KB, int SPLITK, int NYL2, int NT, bool OUT_HALF, bool CONV,
          int LDAW, int LDBH, int LDC,
          size_t ABATCH, size_t BBATCH, size_t CBATCH>
__global__ void __launch_bounds__(NTHREADS, 2)
gemm_f16_ker(const uint32_t* __restrict__ Ag, const __half* __restrict__ Bg,
             void* __restrict__ Cg,
             const float* __restrict__ xp, const float* __restrict__ w1p,
             const float* __restrict__ w2p) {
    extern __shared__ uint32_t sm[];

    const int tid  = threadIdx.x;
    const int lane = tid & 31;
    const int warp = tid >> 5;
    const int g = lane >> 2;
    const int q = lane & 3;
    const int wm = warp & 1;
    const int wn = warp >> 1;

    const uint32_t smem0 = smem_u32(sm);

    const int ar = tid >> 3;
    const int ac = (tid & 7) * 4;
    const int brow = tid >> 4;
    const int bcol = (tid & 15) * 8;

    auto tile_ab = [&](int t, const uint32_t*& A, const __half*& B) {
        int bx = t & 7;
        int by = (t >> 3) & ((1 << NYL2) - 1);
        int bz = t >> (3 + NYL2);
        int zo = bz / SPLITK, sk = bz % SPLITK;
        A = Ag + (size_t)zo * ABATCH + (size_t)sk * (KB * BKH / 2)
               + (size_t)by * BM * LDAW;
        B = Bg + (size_t)zo * BBATCH + (size_t)sk * (KB * BKH) * LDBH
               + (size_t)bx * BN;
    };

    auto load_stage = [&](int slot, const uint32_t* A, const __half* B, int kb) {
        uint32_t sa = smem0 + (uint32_t)slot * STG_BYTES;
        uint32_t sb = sa + A_STG_WORDS * 4;
        const uint32_t* Ak = A + (size_t)kb * (BKH / 2);
        const __half*   Bk = B + (size_t)kb * BKH * LDBH;
        #pragma unroll
        for (int i = 0; i < 8; i++) {
            int r = ar + 16 * i;
            cp16(sa + (uint32_t)(r * LDA_W + ac) * 4u, Ak + (size_t)r * LDAW + ac);
        }
        #pragma unroll
        for (int i = 0; i < 8; i++) {
            int r = brow + 8 * i;
            cp16(sb + (uint32_t)(r * LDB_H + bcol) * 2u, Bk + (size_t)r * LDBH + bcol);
        }
        asm volatile("cp.async.commit_group;\n" ::: "memory");
    };

    const int l8  = lane & 7;
    const int lb8 = (lane >> 3) & 1;
    const int lhi = lane >> 4;
    const uint32_t a_off = (uint32_t)((wm * 64 + l8 + 8 * lb8) * LDA_W + 4 * lhi) * 4u;
    const uint32_t b_off = (uint32_t)((l8 + 8 * lb8) * LDB_H + wn * 64 + 8 * lhi) * 2u;

    float c[4][8][4];
    #pragma unroll
    for (int mt = 0; mt < 4; mt++)
        #pragma unroll
        for (int nt = 0; nt < 8; nt++)
            #pragma unroll
            for (int i = 0; i < 4; i++) c[mt][nt][i] = 0.0f;

    uint32_t afr[2][4][4];
    uint32_t bfr[2][8][2];

    auto load_frags = [&](int slot, int ks, int buf) {
        uint32_t sa = smem0 + (uint32_t)slot * STG_BYTES;
        uint32_t sb = sa + A_STG_WORDS * 4;
        uint32_t abase = sa + a_off + (uint32_t)ks * 32u;
        #pragma unroll
        for (int mt = 0; mt < 4; mt++)
            ldsm4(abase + (uint32_t)(mt * 16 * LDA_W) * 4u, afr[buf][mt]);
        uint32_t bbase = sb + b_off + (uint32_t)(ks * 16 * LDB_H) * 2u;
        #pragma unroll
        for (int p = 0; p < 4; p++)
            ldsm4t(bbase + (uint32_t)p * 32u,
                   bfr[buf][2 * p][0], bfr[buf][2 * p][1],
                   bfr[buf][2 * p + 1][0], bfr[buf][2 * p + 1][1]);
    };

    auto mma_batch = [&](int buf) {
        #pragma unroll
        for (int mt = 0; mt < 4; mt++)
            #pragma unroll
            for (int nt = 0; nt < 8; nt++)
                mma_f16(c[mt][nt], afr[buf][mt], bfr[buf][nt]);
    };

    int t = blockIdx.x;
    const uint32_t* A0; const __half* B0;
    tile_ab(t, A0, B0);
    int t2 = t + (int)gridDim.x;
    const uint32_t* A1 = A0; const __half* B1 = B0;
    if (t2 < NT) tile_ab(t2, A1, B1);

    // expert of a combine tile = t >> 8 (256 tiles per expert, expert-major order)
    int next_conv = 0;
    auto head = [&](int tc, int tn) {
        if constexpr (CONV) {
            int e_hi = (tn < NT) ? (tn >> 8) : (tc >> 8);
            int target = e_hi + 1;
            if (target > E_DIM - 1) target = E_DIM - 1;
            while (next_conv <= target) {
                convert_expert(next_conv, blockIdx.x, tid, xp, w1p, w2p);
                next_conv++;
            }
            wait_expert(e_hi, tid);
        }
    };

    head(t, t2);

    load_stage(0, A0, B0, 0);
    load_stage(1, A0, B0, 1);
    asm volatile("cp.async.wait_group 1;\n" ::: "memory");
    __syncthreads();
    load_frags(0, 0, 0);

    int slot_c = 0, slot_p = 2;

    while (true) {
        #pragma unroll 1
        for (int kb = 0; kb < KB; ++kb) {
            load_frags(slot_c, 1, 1);
            mma_batch(0);
            load_frags(slot_c, 2, 0);
            mma_batch(1);
            load_frags(slot_c, 3, 1);
            mma_batch(0);

            int pf = kb + 2;
            bool pfc = pf < KB;
            bool pfn = !pfc && (t2 < NT);
            if (pfc)      load_stage(slot_p, A0, B0, pf);
            else if (pfn) load_stage(slot_p, A1, B1, pf - KB);
            if (pfc || pfn)
                asm volatile("cp.async.wait_group 1;\n" ::: "memory");
            else
                asm volatile("cp.async.wait_group 0;\n" ::: "memory");
            __syncthreads();
            if (++slot_p == NSTAGE) slot_p = 0;

            int slot_n = (slot_c + 1 == NSTAGE) ? 0 : slot_c + 1;
            if ((kb + 1 < KB) || (t2 < NT)) load_frags(slot_n, 0, 0);
            mma_batch(1);
            slot_c = slot_n;
        }

        // ---- epilogue for tile t ----
        {
            int bx = t & 7;
            int by = (t >> 3) & ((1 << NYL2) - 1);
            int bz = t >> (3 + NYL2);
            if constexpr (OUT_HALF) {
                __half* C = (__half*)Cg + (size_t)bz * CBATCH
                          + (size_t)by * BM * LDC + (size_t)bx * BN;
                #pragma unroll
                for (int mt = 0; mt < 4; mt++) {
                    #pragma unroll
                    for (int nt = 0; nt < 8; nt++) {
                        int r0  = wm * 64 + mt * 16 + g;
                        int col = wn * 64 + nt * 8 + 2 * q;
                        uint32_t h0 = pack_h2(c[mt][nt][0], c[mt][nt][1]);
                        uint32_t h1 = pack_h2(c[mt][nt][2], c[mt][nt][3]);
                        *reinterpret_cast<uint32_t*>(C + (size_t)r0 * LDC + col)       = h0;
                        *reinterpret_cast<uint32_t*>(C + (size_t)(r0 + 8) * LDC + col) = h1;
                    }
                }
            } else {
                float* C = (float*)Cg + (size_t)bz * CBATCH
                         + (size_t)by * BM * LDC + (size_t)bx * BN;
                #pragma unroll
                for (int mt = 0; mt < 4; mt++) {
                    #pragma unroll
                    for (int nt = 0; nt < 8; nt++) {
                        int r0  = wm * 64 + mt * 16 + g;
                        int col = wn * 64 + nt * 8 + 2 * q;
                        float2 v0 = make_float2(c[mt][nt][0], c[mt][nt][1]);
                        float2 v1 = make_float2(c[mt][nt][2], c[mt][nt][3]);
                        *reinterpret_cast<float2*>(C + (size_t)r0 * LDC + col)       = v0;
                        *reinterpret_cast<float2*>(C + (size_t)(r0 + 8) * LDC + col) = v1;
                    }
                }
            }
        }
        if (t2 >= NT) break;

        #pragma unroll
        for (int mt = 0; mt < 4; mt++)
            #pragma unroll
            for (int nt = 0; nt < 8; nt++)
                #pragma unroll
                for (int i = 0; i < 4; i++) c[mt][nt][i] = 0.0f;
        t = t2; A0 = A1; B0 = B1;
        t2 += (int)gridDim.x;
        if (t2 < NT) tile_ab(t2, A1, B1);

        head(t, t2);
    }

    // safety: finish any unconverted slices (needed by other CTAs' waits)
    if constexpr (CONV) {
        while (next_conv < E_DIM) {
            convert_expert(next_conv, blockIdx.x, tid, xp, w1p, w2p);
            next_conv++;
        }
    }
}

// ---- reduce 32 fp16 partials -> fp16 wsum halves [k][n] ----
__global__ void reduce_experts_ker() {
    int idx = blockIdx.x * blockDim.x + threadIdx.x;
    const uint4* p = reinterpret_cast<const uint4*>(g_part);
    float acc[8];
    #pragma unroll
    for (int j = 0; j < 8; j++) acc[j] = 0.0f;
    #pragma unroll
    for (int e = 0; e < E_DIM * SPLITK_C; e++) {
        uint4 v = p[(size_t)e * (H_DIM * H_DIM / 8) + idx];
        const __half2* h = reinterpret_cast<const __half2*>(&v);
        #pragma unroll
        for (int j = 0; j < 4; j++) {
            float2 f = __half22float2(h[j]);
            acc[2 * j]     += f.x;
            acc[2 * j + 1] += f.y;
        }
    }
    uint4 o;
    o.x = pack_h2(acc[0], acc[1]);
    o.y = pack_h2(acc[2], acc[3]);
    o.z = pack_h2(acc[4], acc[5]);
    o.w = pack_h2(acc[6], acc[7]);
    reinterpret_cast<uint4*>(g_wsh)[idx] = o;
}

// ================= launch =================
extern "C" void kernel_launch(void* const* d_in, const int* in_sizes, int n_in,
                              void* d_out, int out_size) {
    const float* x  = (const float*)d_in[0];
    const float* w1 = (const float*)d_in[1];   // [E][H][N]
    const float* w2 = (const float*)d_in[2];   // [E][N][H]
    float* out = (float*)d_out;                // [A][M][H]

    uint32_t* w1h = nullptr; cudaGetSymbolAddress((void**)&w1h, g_w1h);
    __half*   w2h = nullptr; cudaGetSymbolAddress((void**)&w2h, g_w2h);
    uint32_t* xh  = nullptr; cudaGetSymbolAddress((void**)&xh,  g_xh);
    __half*   part = nullptr; cudaGetSymbolAddress((void**)&part, g_part);
    __half*   wsh = nullptr; cudaGetSymbolAddress((void**)&wsh, g_wsh);

    constexpr int KB_C = (N_DIM / BKH) / SPLITK_C;
    auto* comb = gemm_f16_ker<KB_C, SPLITK_C, 3, 2048, true, true,
                              N_DIM / 2, H_DIM, H_DIM,
                              (size_t)H_DIM * (N_DIM / 2),
                              (size_t)N_DIM * H_DIM,
                              (size_t)H_DIM * H_DIM>;
    constexpr int KB_A = H_DIM / BKH;
    auto* appl = gemm_f16_ker<KB_A, 1, 5, 256, false, false,
                              H_DIM / 2, H_DIM, H_DIM,
                              (size_t)0, (size_t)0, (size_t)0>;

    cudaFuncSetAttribute((const void*)comb,
                         cudaFuncAttributeMaxDynamicSharedMemorySize, SMEM_DYN);
    cudaFuncSetAttribute((const void*)appl,
                         cudaFuncAttributeMaxDynamicSharedMemorySize, SMEM_DYN);

    // 0) reset conversion flags (graph replays reuse device globals)
    zero_flags_ker<<<1, 32>>>();

    // 1) persistent combine with fused fp16 conversion producer
    comb<<<GRID_P, NTHREADS, SMEM_DYN>>>(w1h, w2h, part, x, w1, w2);

    // 2) reduce partials -> fp16 wsum [k][n]
    reduce_experts_ker<<<(H_DIM * H_DIM / 8) / 256, 256>>>();

    // 3) apply: out = xh @ wsum  (fp32 output)
    appl<<<256, NTHREADS, SMEM_DYN>>>(xh, wsh, (void*)out, nullptr, nullptr, nullptr);
}

// round 15
// speedup vs baseline: 1.1387x; 1.1387x over previous
#include <cuda_runtime.h>
#include <cuda_fp16.h>
#include <cstdint>
#include <cstddef>

// ---------------- problem dims ----------------
#define A_DIM 4
#define M_DIM 1024
#define H_DIM 1024
#define E_DIM 8
#define N_DIM 4096
#define SPLITK_C 4

// ---------------- tile config ----------------
#define BM 128
#define BN 128
#define BKH 64
#define NSTAGE 3
#define NTHREADS 128
#define LDA_W 36
#define LDB_H 136
#define A_STG_WORDS (BM * LDA_W)
#define B_STG_WORDS (BKH * LDB_H / 2)
#define STG_WORDS   (A_STG_WORDS + B_STG_WORDS)
#define STG_BYTES   (STG_WORDS * 4)                /* 35840 B */
#define SMEM_DYN    (NSTAGE * STG_BYTES)           /* 107520 B -> 2 CTA/SM */
#define GRID_P      296

// ---------------- device scratch ----------------
__device__ uint32_t g_w1h[(size_t)E_DIM * H_DIM * (N_DIM / 2)];
__device__ __half   g_w2h[(size_t)E_DIM * N_DIM * H_DIM];
__device__ uint32_t g_xh [(size_t)A_DIM * M_DIM * (H_DIM / 2)];
__device__ __half   g_part[(size_t)E_DIM * SPLITK_C * H_DIM * H_DIM];  // 64 MB fp16
__device__ __half   g_wsh[(size_t)H_DIM * H_DIM];

// ---------------- helpers ----------------
__device__ __forceinline__ uint32_t smem_u32(const void* p) {
    uint32_t a;
    asm("{ .reg .u64 t; cvta.to.shared.u64 t, %1; cvt.u32.u64 %0, t; }" : "=r"(a) : "l"(p));
    return a;
}
__device__ __forceinline__ uint32_t pack_h2(float lo, float hi) {
    __half2 h = __float22half2_rn(make_float2(lo, hi));
    return *reinterpret_cast<uint32_t*>(&h);
}
__device__ __forceinline__ void cp16(uint32_t dst, const void* src) {
    asm volatile("cp.async.cg.shared.global [%0], [%1], 16;\n"
                 :: "r"(dst), "l"(__cvta_generic_to_global(src)) : "memory");
}
__device__ __forceinline__ void mma_f16(float* c, const uint32_t* a, const uint32_t* b) {
    asm volatile(
        "mma.sync.aligned.m16n8k16.row.col.f32.f16.f16.f32 "
        "{%0,%1,%2,%3}, {%4,%5,%6,%7}, {%8,%9}, {%0,%1,%2,%3};"
        : "+f"(c[0]), "+f"(c[1]), "+f"(c[2]), "+f"(c[3])
        : "r"(a[0]), "r"(a[1]), "r"(a[2]), "r"(a[3]), "r"(b[0]), "r"(b[1]));
}
__device__ __forceinline__ void ldsm4(uint32_t addr, uint32_t* r) {
    asm volatile("ldmatrix.sync.aligned.m8n8.x4.shared.b16 {%0,%1,%2,%3}, [%4];"
                 : "=r"(r[0]), "=r"(r[1]), "=r"(r[2]), "=r"(r[3]) : "r"(addr));
}
__device__ __forceinline__ void ldsm4t(uint32_t addr, uint32_t& r0, uint32_t& r1,
                                       uint32_t& r2, uint32_t& r3) {
    asm volatile("ldmatrix.sync.aligned.m8n8.x4.trans.shared.b16 {%0,%1,%2,%3}, [%4];"
                 : "=r"(r0), "=r"(r1), "=r"(r2), "=r"(r3) : "r"(addr));
}
__device__ __forceinline__ float4 ldcs4(const float4* p) {
    float4 v;
    asm volatile("ld.global.cs.v4.f32 {%0,%1,%2,%3}, [%4];"
                 : "=f"(v.x), "=f"(v.y), "=f"(v.z), "=f"(v.w)
                 : "l"(__cvta_generic_to_global(p)));
    return v;
}

// ---- prep: single fused fp32 -> fp16 conversion over w1, w2, x ----
// Source reads use evict-first (.cs): fp32 inputs are read exactly once, so
// keep L2 capacity for the fp16 outputs the combine GEMM re-reads 8x.
#define N4_W1 ((size_t)E_DIM * H_DIM * N_DIM / 4)
#define N4_W2 ((size_t)E_DIM * N_DIM * H_DIM / 4)
#define N4_X  ((size_t)A_DIM * M_DIM * H_DIM / 4)
__global__ void conv_all_ker(const float* __restrict__ x,
                             const float* __restrict__ w1,
                             const float* __restrict__ w2) {
    size_t i = (size_t)blockIdx.x * blockDim.x + threadIdx.x;
    const float* src; uint32_t* dst; size_t j;
    if (i < N4_W1)              { src = w1; dst = g_w1h;            j = i; }
    else if (i < N4_W1 + N4_W2) { src = w2; dst = (uint32_t*)g_w2h; j = i - N4_W1; }
    else if (i < N4_W1 + N4_W2 + N4_X)
                                { src = x;  dst = g_xh;             j = i - N4_W1 - N4_W2; }
    else return;
    float4 v = ldcs4(reinterpret_cast<const float4*>(src) + j);
    uint2 o;
    o.x = pack_h2(v.x, v.y);
    o.y = pack_h2(v.z, v.w);
    reinterpret_cast<uint2*>(dst)[j] = o;
}

// =============================================================================
// Persistent fp16 GEMM. A: fp16 words [m][k/2]. B: fp16 halves [k][n].
// OUT_HALF: write C as fp16 (combine partials) or fp32 (final output).
// =============================================================================
template <int KB, int SPLITK, int NYL2, int NT, bool OUT_HALF,
          int LDAW, int LDBH, int LDC,
          size_t ABATCH, size_t BBATCH, size_t CBATCH>
__global__ void __launch_bounds__(NTHREADS, 2)
gemm_f16_ker(const uint32_t* __restrict__ Ag, const __half* __restrict__ Bg,
             void* __restrict__ Cg) {
    extern __shared__ uint32_t sm[];

    const int tid  = threadIdx.x;
    const int lane = tid & 31;
    const int warp = tid >> 5;
    const int g = lane >> 2;
    const int q = lane & 3;
    const int wm = warp & 1;
    const int wn = warp >> 1;

    const uint32_t smem0 = smem_u32(sm);

    const int ar = tid >> 3;
    const int ac = (tid & 7) * 4;
    const int brow = tid >> 4;
    const int bcol = (tid & 15) * 8;

    auto tile_ab = [&](int t, const uint32_t*& A, const __half*& B) {
        int bx = t & 7;
        int by = (t >> 3) & ((1 << NYL2) - 1);
        int bz = t >> (3 + NYL2);
        int zo = bz / SPLITK, sk = bz % SPLITK;
        A = Ag + (size_t)zo * ABATCH + (size_t)sk * (KB * BKH / 2)
               + (size_t)by * BM * LDAW;
        B = Bg + (size_t)zo * BBATCH + (size_t)sk * (KB * BKH) * LDBH
               + (size_t)bx * BN;
    };

    auto load_stage = [&](int slot, const uint32_t* A, const __half* B, int kb) {
        uint32_t sa = smem0 + (uint32_t)slot * STG_BYTES;
        uint32_t sb = sa + A_STG_WORDS * 4;
        const uint32_t* Ak = A + (size_t)kb * (BKH / 2);
        const __half*   Bk = B + (size_t)kb * BKH * LDBH;
        #pragma unroll
        for (int i = 0; i < 8; i++) {
            int r = ar + 16 * i;
            cp16(sa + (uint32_t)(r * LDA_W + ac) * 4u, Ak + (size_t)r * LDAW + ac);
        }
        #pragma unroll
        for (int i = 0; i < 8; i++) {
            int r = brow + 8 * i;
            cp16(sb + (uint32_t)(r * LDB_H + bcol) * 2u, Bk + (size_t)r * LDBH + bcol);
        }
        asm volatile("cp.async.commit_group;\n" ::: "memory");
    };

    const int l8  = lane & 7;
    const int lb8 = (lane >> 3) & 1;
    const int lhi = lane >> 4;
    const uint32_t a_off = (uint32_t)((wm * 64 + l8 + 8 * lb8) * LDA_W + 4 * lhi) * 4u;
    const uint32_t b_off = (uint32_t)((l8 + 8 * lb8) * LDB_H + wn * 64 + 8 * lhi) * 2u;

    float c[4][8][4];
    #pragma unroll
    for (int mt = 0; mt < 4; mt++)
        #pragma unroll
        for (int nt = 0; nt < 8; nt++)
            #pragma unroll
            for (int i = 0; i < 4; i++) c[mt][nt][i] = 0.0f;

    uint32_t afr[2][4][4];
    uint32_t bfr[2][8][2];

    auto load_frags = [&](int slot, int ks, int buf) {
        uint32_t sa = smem0 + (uint32_t)slot * STG_BYTES;
        uint32_t sb = sa + A_STG_WORDS * 4;
        uint32_t abase = sa + a_off + (uint32_t)ks * 32u;
        #pragma unroll
        for (int mt = 0; mt < 4; mt++)
            ldsm4(abase + (uint32_t)(mt * 16 * LDA_W) * 4u, afr[buf][mt]);
        uint32_t bbase = sb + b_off + (uint32_t)(ks * 16 * LDB_H) * 2u;
        #pragma unroll
        for (int p = 0; p < 4; p++)
            ldsm4t(bbase + (uint32_t)p * 32u,
                   bfr[buf][2 * p][0], bfr[buf][2 * p][1],
                   bfr[buf][2 * p + 1][0], bfr[buf][2 * p + 1][1]);
    };

    auto mma_batch = [&](int buf) {
        #pragma unroll
        for (int mt = 0; mt < 4; mt++)
            #pragma unroll
            for (int nt = 0; nt < 8; nt++)
                mma_f16(c[mt][nt], afr[buf][mt], bfr[buf][nt]);
    };

    int t = blockIdx.x;
    if (t >= NT) return;
    const uint32_t* A0; const __half* B0;
    tile_ab(t, A0, B0);
    int t2 = t + (int)gridDim.x;
    const uint32_t* A1 = A0; const __half* B1 = B0;
    if (t2 < NT) tile_ab(t2, A1, B1);

    load_stage(0, A0, B0, 0);
    load_stage(1, A0, B0, 1);
    asm volatile("cp.async.wait_group 1;\n" ::: "memory");
    __syncthreads();
    load_frags(0, 0, 0);

    int slot_c = 0, slot_p = 2;

    while (true) {
        #pragma unroll 1
        for (int kb = 0; kb < KB; ++kb) {
            load_frags(slot_c, 1, 1);
            mma_batch(0);
            load_frags(slot_c, 2, 0);
            mma_batch(1);
            load_frags(slot_c, 3, 1);
            mma_batch(0);

            int pf = kb + 2;
            bool pfc = pf < KB;
            bool pfn = !pfc && (t2 < NT);
            if (pfc)      load_stage(slot_p, A0, B0, pf);
            else if (pfn) load_stage(slot_p, A1, B1, pf - KB);
            if (pfc || pfn)
                asm volatile("cp.async.wait_group 1;\n" ::: "memory");
            else
                asm volatile("cp.async.wait_group 0;\n" ::: "memory");
            __syncthreads();
            if (++slot_p == NSTAGE) slot_p = 0;

            int slot_n = (slot_c + 1 == NSTAGE) ? 0 : slot_c + 1;
            if ((kb + 1 < KB) || (t2 < NT)) load_frags(slot_n, 0, 0);
            mma_batch(1);
            slot_c = slot_n;
        }

        // ---- epilogue for tile t ----
        {
            int bx = t & 7;
            int by = (t >> 3) & ((1 << NYL2) - 1);
            int bz = t >> (3 + NYL2);
            if constexpr (OUT_HALF) {
                __half* C = (__half*)Cg + (size_t)bz * CBATCH
                          + (size_t)by * BM * LDC + (size_t)bx * BN;
                #pragma unroll
                for (int mt = 0; mt < 4; mt++) {
                    #pragma unroll
                    for (int nt = 0; nt < 8; nt++) {
                        int r0  = wm * 64 + mt * 16 + g;
                        int col = wn * 64 + nt * 8 + 2 * q;
                        uint32_t h0 = pack_h2(c[mt][nt][0], c[mt][nt][1]);
                        uint32_t h1 = pack_h2(c[mt][nt][2], c[mt][nt][3]);
                        *reinterpret_cast<uint32_t*>(C + (size_t)r0 * LDC + col)       = h0;
                        *reinterpret_cast<uint32_t*>(C + (size_t)(r0 + 8) * LDC + col) = h1;
                    }
                }
            } else {
                float* C = (float*)Cg + (size_t)bz * CBATCH
                         + (size_t)by * BM * LDC + (size_t)bx * BN;
                #pragma unroll
                for (int mt = 0; mt < 4; mt++) {
                    #pragma unroll
                    for (int nt = 0; nt < 8; nt++) {
                        int r0  = wm * 64 + mt * 16 + g;
                        int col = wn * 64 + nt * 8 + 2 * q;
                        float2 v0 = make_float2(c[mt][nt][0], c[mt][nt][1]);
                        float2 v1 = make_float2(c[mt][nt][2], c[mt][nt][3]);
                        *reinterpret_cast<float2*>(C + (size_t)r0 * LDC + col)       = v0;
                        *reinterpret_cast<float2*>(C + (size_t)(r0 + 8) * LDC + col) = v1;
                    }
                }
            }
        }
        if (t2 >= NT) break;

        #pragma unroll
        for (int mt = 0; mt < 4; mt++)
            #pragma unroll
            for (int nt = 0; nt < 8; nt++)
                #pragma unroll
                for (int i = 0; i < 4; i++) c[mt][nt][i] = 0.0f;
        t = t2; A0 = A1; B0 = B1;
        t2 += (int)gridDim.x;
        if (t2 < NT) tile_ab(t2, A1, B1);
    }
}

// ---- reduce 32 fp16 partials -> fp16 wsum halves [k][n] ----
__global__ void reduce_experts_ker() {
    int idx = blockIdx.x * blockDim.x + threadIdx.x;
    const uint4* p = reinterpret_cast<const uint4*>(g_part);
    float acc[8];
    #pragma unroll
    for (int j = 0; j < 8; j++) acc[j] = 0.0f;
    #pragma unroll
    for (int e = 0; e < E_DIM * SPLITK_C; e++) {
        uint4 v = p[(size_t)e * (H_DIM * H_DIM / 8) + idx];
        const __half2* h = reinterpret_cast<const __half2*>(&v);
        #pragma unroll
        for (int j = 0; j < 4; j++) {
            float2 f = __half22float2(h[j]);
            acc[2 * j]     += f.x;
            acc[2 * j + 1] += f.y;
        }
    }
    uint4 o;
    o.x = pack_h2(acc[0], acc[1]);
    o.y = pack_h2(acc[2], acc[3]);
    o.z = pack_h2(acc[4], acc[5]);
    o.w = pack_h2(acc[6], acc[7]);
    reinterpret_cast<uint4*>(g_wsh)[idx] = o;
}

// ================= launch =================
extern "C" void kernel_launch(void* const* d_in, const int* in_sizes, int n_in,
                              void* d_out, int out_size) {
    const float* x  = (const float*)d_in[0];
    const float* w1 = (const float*)d_in[1];   // [E][H][N]
    const float* w2 = (const float*)d_in[2];   // [E][N][H]
    float* out = (float*)d_out;                // [A][M][H]

    uint32_t* w1h = nullptr; cudaGetSymbolAddress((void**)&w1h, g_w1h);
    __half*   w2h = nullptr; cudaGetSymbolAddress((void**)&w2h, g_w2h);
    uint32_t* xh  = nullptr; cudaGetSymbolAddress((void**)&xh,  g_xh);
    __half*   part = nullptr; cudaGetSymbolAddress((void**)&part, g_part);
    __half*   wsh = nullptr; cudaGetSymbolAddress((void**)&wsh, g_wsh);

    constexpr int KB_C = (N_DIM / BKH) / SPLITK_C;
    auto* comb = gemm_f16_ker<KB_C, SPLITK_C, 3, 2048, true,
                              N_DIM / 2, H_DIM, H_DIM,
                              (size_t)H_DIM * (N_DIM / 2),
                              (size_t)N_DIM * H_DIM,
                              (size_t)H_DIM * H_DIM>;
    constexpr int KB_A = H_DIM / BKH;
    auto* appl = gemm_f16_ker<KB_A, 1, 5, 256, false,
                              H_DIM / 2, H_DIM, H_DIM,
                              (size_t)0, (size_t)0, (size_t)0>;

    cudaFuncSetAttribute((const void*)comb,
                         cudaFuncAttributeMaxDynamicSharedMemorySize, SMEM_DYN);
    cudaFuncSetAttribute((const void*)appl,
                         cudaFuncAttributeMaxDynamicSharedMemorySize, SMEM_DYN);

    // 0) fused fp16 conversion of w1, w2, x (evict-first source reads)
    size_t n4_total = N4_W1 + N4_W2 + N4_X;
    conv_all_ker<<<(int)((n4_total + 511) / 512), 512>>>(x, w1, w2);

    // 1) persistent split-K combine -> fp16 partials
    comb<<<GRID_P, NTHREADS, SMEM_DYN>>>(w1h, w2h, part);

    // 2) reduce partials -> fp16 wsum [k][n]
    reduce_experts_ker<<<(H_DIM * H_DIM / 8) / 256, 256>>>();

    // 3) apply: out = xh @ wsum  (fp32 output)
    appl<<<256, NTHREADS, SMEM_DYN>>>(xh, wsh, (void*)out);
}